// round 15
// baseline (speedup 1.0000x reference)
#include <cuda_runtime.h>
#include <cuda_bf16.h>
#include <math.h>

// Problem constants
#define NB   64
#define LSEQ 512
#define HD   1024
#define LH   (LSEQ * HD)
#define NBLK 128          // 4 n-groups (16 rows) x 32 o-tiles (32 cols)
#define SA   522          // ULL row stride for As3/Bs (bank spread, even)

typedef unsigned long long ULL;

// Octet arrival counters: g_oct[ng][oct] (32B apart). Producer (ng,ot) arrives
// on oct = ot>>3 once per step => counter +8 per step, +4096 per replay.
__device__ unsigned g_oct[4 * 4 * 8];
__device__ unsigned g_end;     // end-of-replay quiesce
__device__ unsigned g_epoch;   // completed replay count

// ---------------------------------------------------------------------------
// Packed f32x2 helpers (FFMA2 — 2 exact fp32 MACs per issue)
// ---------------------------------------------------------------------------
__device__ __forceinline__ void ffma2(ULL& d, ULL a, ULL b)
{
    asm("fma.rn.f32x2 %0, %1, %2, %0;" : "+l"(d) : "l"(a), "l"(b));
}
__device__ __forceinline__ ULL rep2(float v)
{
    ULL r;
    asm("mov.b64 %0, {%1, %1};" : "=l"(r) : "f"(v));
    return r;
}
__device__ __forceinline__ ULL pack2(float x, float y)
{
    ULL r;
    asm("mov.b64 %0, {%1, %2};" : "=l"(r) : "f"(x), "f"(y));
    return r;
}
__device__ __forceinline__ float2 unpack2(ULL v)
{
    float2 f;
    asm("mov.b64 {%0, %1}, %2;" : "=f"(f.x), "=f"(f.y) : "l"(v));
    return f;
}

// ---------------------------------------------------------------------------
// Kernel 1: xh[m][o] = sum_h emb[x[m]][h] * Wxh[o][h] + bxh[o] + bhh[o]
// (unchanged — 128x128 tile, 8x8 microtile on f32x2, at its FFMA2 floor)
// ---------------------------------------------------------------------------
__global__ __launch_bounds__(256) void xh_kernel(
    const int* __restrict__ x, const float* __restrict__ emb,
    const float* __restrict__ Wxh, const float* __restrict__ bxh,
    const float* __restrict__ bhh, float* __restrict__ out)
{
    __shared__ float As[16][132];
    __shared__ float Bs[16][132];
    __shared__ int   toks[128];

    const int m0 = blockIdx.y * 128;
    const int o0 = blockIdx.x * 128;
    const int tid = threadIdx.x;

    if (tid < 128) toks[tid] = x[m0 + tid];
    __syncthreads();

    const int lr  = tid & 127;
    const int lkq = (tid >> 7) << 3;
    const int tm  = (tid >> 4) << 3;
    const int tc  = (tid & 15) << 2;

    const float* Erow = emb + (size_t)toks[lr] * HD + lkq;
    const float* Wrow = Wxh + (size_t)(o0 + lr) * HD + lkq;

    ULL acc[8][4];
    #pragma unroll
    for (int i = 0; i < 8; i++)
        #pragma unroll
        for (int j = 0; j < 4; j++) acc[i][j] = 0ULL;

    for (int k0 = 0; k0 < HD; k0 += 16) {
        const float4 a0 = *(const float4*)(Erow + k0);
        const float4 a1 = *(const float4*)(Erow + k0 + 4);
        const float4 b0 = *(const float4*)(Wrow + k0);
        const float4 b1 = *(const float4*)(Wrow + k0 + 4);
        __syncthreads();
        As[lkq + 0][lr] = a0.x; As[lkq + 1][lr] = a0.y;
        As[lkq + 2][lr] = a0.z; As[lkq + 3][lr] = a0.w;
        As[lkq + 4][lr] = a1.x; As[lkq + 5][lr] = a1.y;
        As[lkq + 6][lr] = a1.z; As[lkq + 7][lr] = a1.w;
        Bs[lkq + 0][lr] = b0.x; Bs[lkq + 1][lr] = b0.y;
        Bs[lkq + 2][lr] = b0.z; Bs[lkq + 3][lr] = b0.w;
        Bs[lkq + 4][lr] = b1.x; Bs[lkq + 5][lr] = b1.y;
        Bs[lkq + 6][lr] = b1.z; Bs[lkq + 7][lr] = b1.w;
        __syncthreads();

        #pragma unroll
        for (int kk = 0; kk < 16; kk++) {
            const float4 av0 = *(const float4*)&As[kk][tm];
            const float4 av1 = *(const float4*)&As[kk][tm + 4];
            ULL ar[8];
            ar[0] = rep2(av0.x); ar[1] = rep2(av0.y);
            ar[2] = rep2(av0.z); ar[3] = rep2(av0.w);
            ar[4] = rep2(av1.x); ar[5] = rep2(av1.y);
            ar[6] = rep2(av1.z); ar[7] = rep2(av1.w);
            const ulonglong2 bq0 = *(const ulonglong2*)&Bs[kk][tc];
            const ulonglong2 bq1 = *(const ulonglong2*)&Bs[kk][64 + tc];
            #pragma unroll
            for (int i = 0; i < 8; i++) {
                ffma2(acc[i][0], ar[i], bq0.x);
                ffma2(acc[i][1], ar[i], bq0.y);
                ffma2(acc[i][2], ar[i], bq1.x);
                ffma2(acc[i][3], ar[i], bq1.y);
            }
        }
    }

    const float4 bxa = *(const float4*)&bxh[o0 + tc];
    const float4 bxb = *(const float4*)&bxh[o0 + 64 + tc];
    const float4 bha = *(const float4*)&bhh[o0 + tc];
    const float4 bhb = *(const float4*)&bhh[o0 + 64 + tc];
    const float bs0[4] = {bxa.x + bha.x, bxa.y + bha.y, bxa.z + bha.z, bxa.w + bha.w};
    const float bs1[4] = {bxb.x + bhb.x, bxb.y + bhb.y, bxb.z + bhb.z, bxb.w + bhb.w};

    #pragma unroll
    for (int i = 0; i < 8; i++) {
        const float2 p0 = unpack2(acc[i][0]);
        const float2 p1 = unpack2(acc[i][1]);
        const float2 p2 = unpack2(acc[i][2]);
        const float2 p3 = unpack2(acc[i][3]);
        float4 v0, v1;
        v0.x = p0.x + bs0[0]; v0.y = p0.y + bs0[1];
        v0.z = p1.x + bs0[2]; v0.w = p1.y + bs0[3];
        v1.x = p2.x + bs1[0]; v1.y = p2.y + bs1[1];
        v1.z = p3.x + bs1[2]; v1.w = p3.y + bs1[3];
        float* po = &out[(size_t)(m0 + tm + i) * HD + o0 + tc];
        *(float4*)po        = v0;
        *(float4*)(po + 64) = v1;
    }
}

// ---------------------------------------------------------------------------
// Kernel 2: persistent recurrence — direct-output warps, no cross-warp reduce.
// Block bx: ng = bx>>5 (rows [16ng,+16)), ot = bx&31 (cols [32ot,+32)).
// Warp w: rg = w&3 -> rows [4rg,+4); ch = w>>2 -> cols [16ch,+16).
// Lane: r2 = l&1 (row pair), c8 = (l>>1)&7 (col pair), khalf = l>>4 (k half).
// Each lane: 2r x 2c outputs over its 512-k half; shfl.xor 16 combines halves.
// Staging: warp-pair g = w>>1 stages octet g (k [256g,+256)) after polling its
// 8 producers; named barrier 1+g (arrive by stagers, sync by consumers before
// the GEMM half that reads octet g). One __syncthreads per step.
// Smem: As3 ULL[16][SA] | Bs ULL[32][SA]  (~200 KB).
// ---------------------------------------------------------------------------
#define RNN_SMEM_BYTES ((16 * SA + 32 * SA) * 8)

__global__ __launch_bounds__(256) void rnn_persistent(
    const float* __restrict__ Whh, float* __restrict__ out)
{
    extern __shared__ char smraw[];
    ULL* As3 = (ULL*)smraw;          // [n][kp]   n=0..15, stride SA
    ULL* Bs  = As3 + 16 * SA;        // [col][kp] col=0..31, stride SA

    const int bx   = blockIdx.x;
    const int ng   = bx >> 5;
    const int ot   = bx & 31;
    const int n0   = ng * 16;
    const int o0   = ot * 32;
    const int tid  = threadIdx.x;
    const int w    = tid >> 5;
    const int lane = tid & 31;
    const int rg   = w & 3;
    const int ch   = w >> 2;
    const int r2   = lane & 1;
    const int c8   = (lane >> 1) & 7;
    const int khalf = lane >> 4;
    const int g    = w >> 1;                  // staged octet of my warp pair
    const int idx  = ((w & 1) << 5) | lane;   // 0..63 within pair
    const int myoct = ot >> 3;

    // ---- load W_hh slice once: Bs[col][kp] ----
    {
        const int col = tid & 31;
        const int cnk = tid >> 5;             // 8 chunks of 128 k
        const float* wr = Whh + (size_t)(o0 + col) * HD + cnk * 128;
        #pragma unroll
        for (int m = 0; m < 32; m++) {
            const float4 v = *(const float4*)(wr + 4 * m);
            const int kp = cnk * 64 + 2 * m;
            ulonglong2 u;
            u.x = pack2(v.x, v.y);
            u.y = pack2(v.z, v.w);
            *(ulonglong2*)&Bs[(size_t)col * SA + kp] = u;
        }
    }

    // ---- epoch -> counter base ----
    __shared__ unsigned s_e;
    if (tid == 0) s_e = *(volatile unsigned*)&g_epoch;
    __syncthreads();
    const unsigned e = s_e;
    const unsigned base = 4096u * e;

    // output rows/cols for this lane
    const int row0 = n0 + 4 * rg + 2 * r2;    // rows row0, row0+1
    const int cb   = o0 + 16 * ch + 2 * c8;   // cols cb, cb+1

    // staging: my float4 column within octet g
    const int kst = (g << 8) + (idx << 2);    // absolute k of my float4
    const int kp0 = kst >> 1;

    // ---- t = 0: h_0 = tanh(xh_0) on my outputs (khalf 0 lanes only) ----
    if (khalf == 0) {
        #pragma unroll
        for (int r = 0; r < 2; r++) {
            float* p = out + (size_t)(row0 + r) * LH + cb;
            float2 v = *(float2*)p;
            v.x = tanhf(v.x); v.y = tanhf(v.y);
            *(float2*)p = v;
        }
    }
    __threadfence();
    __syncthreads();
    if (tid == 0) atomicAdd(&g_oct[(ng * 4 + myoct) * 8], 1u);

    for (int t = 1; t < LSEQ; t++) {
        // xh prefetch (only khalf 0 lanes need it; each location owned by one lane)
        float2 xh0, xh1;
        if (khalf == 0) {
            xh0 = *(const float2*)(out + (size_t)row0 * LH + (size_t)t * HD + cb);
            xh1 = *(const float2*)(out + (size_t)(row0 + 1) * LH + (size_t)t * HD + cb);
        }

        // ---- pair-scoped wait + stage octet g ----
        if (lane == 0) {
            const unsigned tgt = base + 8u * (unsigned)t;
            while ((int)(*(volatile unsigned*)&g_oct[(ng * 4 + g) * 8] - tgt) < 0) { }
        }
        __syncwarp();
        {
            const float* hbase = out + (size_t)(t - 1) * HD + kst;
            #pragma unroll
            for (int jj = 0; jj < 16; jj += 8) {
                float4 vb[8];
                #pragma unroll
                for (int j2 = 0; j2 < 8; j2++)
                    vb[j2] = __ldcg((const float4*)(hbase + (size_t)(n0 + jj + j2) * LH));
                #pragma unroll
                for (int j2 = 0; j2 < 8; j2++) {
                    ulonglong2 u;
                    u.x = pack2(vb[j2].x, vb[j2].y);
                    u.y = pack2(vb[j2].z, vb[j2].w);
                    *(ulonglong2*)&As3[(size_t)(jj + j2) * SA + kp0] = u;
                }
            }
        }
        // publish my octet; sync with co-stager (pair barrier 5+g, 64 threads)
        asm volatile("bar.arrive %0, %1;" :: "r"(1 + g), "r"(256) : "memory");
        asm volatile("bar.sync %0, %1;"   :: "r"(5 + g), "r"(64)  : "memory");

        // ---- GEMM: lane's k half, two 128-kp quarters gated by octet bars ----
        ULL accE[2][2], accO[2][2];
        #pragma unroll
        for (int i = 0; i < 2; i++)
            #pragma unroll
            for (int j = 0; j < 2; j++) { accE[i][j] = 0ULL; accO[i][j] = 0ULL; }

        const ULL* aR0 = As3 + (size_t)(4 * rg + 2 * r2) * SA + 256 * khalf;
        const ULL* aR1 = aR0 + SA;
        const ULL* bC0 = Bs + (size_t)(16 * ch + 2 * c8) * SA + 256 * khalf;
        const ULL* bC1 = bC0 + SA;

        #pragma unroll
        for (int h = 0; h < 2; h++) {
            // half h touches octets {2*khalf + h} across lanes => {0,2} then {1,3}
            if (h == 0) {
                if (g != 0) asm volatile("bar.sync %0, %1;" :: "r"(1), "r"(256) : "memory");
                if (g != 2) asm volatile("bar.sync %0, %1;" :: "r"(3), "r"(256) : "memory");
            } else {
                if (g != 1) asm volatile("bar.sync %0, %1;" :: "r"(2), "r"(256) : "memory");
                if (g != 3) asm volatile("bar.sync %0, %1;" :: "r"(4), "r"(256) : "memory");
            }
            #pragma unroll 8
            for (int j = 64 * h; j < 64 * h + 64; j++) {
                const ulonglong2 a0 = *(const ulonglong2*)(aR0 + 2 * j);
                const ulonglong2 a1 = *(const ulonglong2*)(aR1 + 2 * j);
                const ulonglong2 b0 = *(const ulonglong2*)(bC0 + 2 * j);
                const ulonglong2 b1 = *(const ulonglong2*)(bC1 + 2 * j);
                ffma2(accE[0][0], a0.x, b0.x); ffma2(accO[0][0], a0.y, b0.y);
                ffma2(accE[0][1], a0.x, b1.x); ffma2(accO[0][1], a0.y, b1.y);
                ffma2(accE[1][0], a1.x, b0.x); ffma2(accO[1][0], a1.y, b0.y);
                ffma2(accE[1][1], a1.x, b1.x); ffma2(accO[1][1], a1.y, b1.y);
            }
        }

        // ---- combine k-halves via shfl, tanh, write h_t ----
        float tot[2][2];
        #pragma unroll
        for (int i = 0; i < 2; i++)
            #pragma unroll
            for (int j = 0; j < 2; j++) {
                const float2 pe = unpack2(accE[i][j]);
                const float2 po = unpack2(accO[i][j]);
                const float s = (pe.x + pe.y) + (po.x + po.y);
                tot[i][j] = s + __shfl_xor_sync(0xffffffffu, s, 16);
            }
        if (khalf == 0) {
            float2 h0v, h1v;
            h0v.x = tanhf(tot[0][0] + xh0.x);
            h0v.y = tanhf(tot[0][1] + xh0.y);
            h1v.x = tanhf(tot[1][0] + xh1.x);
            h1v.y = tanhf(tot[1][1] + xh1.y);
            *(float2*)(out + (size_t)row0 * LH + (size_t)t * HD + cb)       = h0v;
            *(float2*)(out + (size_t)(row0 + 1) * LH + (size_t)t * HD + cb) = h1v;
        }

        __threadfence();
        __syncthreads();   // h_t visible; As3 WAR safe; named bars all completed
        if (tid == 0) atomicAdd(&g_oct[(ng * 4 + myoct) * 8], 1u);
    }

    // ---- end-of-replay quiesce: only block 0's thread 0 blocks ----
    if (tid == 0) atomicAdd(&g_end, 1u);
    if (bx == 0 && tid == 0) {
        const unsigned tgt = 128u * (e + 1u);
        while ((int)(*(volatile unsigned*)&g_end - tgt) < 0) { }
        *(volatile unsigned*)&g_epoch = e + 1u;
    }
}

// ---------------------------------------------------------------------------
// Launch: metadata order is x, emb, W_hh_w, W_hh_b, W_xh_w, W_xh_b.
// Graph: exactly 2 kernel nodes.
// ---------------------------------------------------------------------------
extern "C" void kernel_launch(void* const* d_in, const int* in_sizes, int n_in,
                              void* d_out, int out_size)
{
    const int*   x     = (const int*)  d_in[0];
    const float* emb   = (const float*)d_in[1];
    const float* Whh_w = (const float*)d_in[2];
    const float* Whh_b = (const float*)d_in[3];
    const float* Wxh_w = (const float*)d_in[4];
    const float* Wxh_b = (const float*)d_in[5];
    float* out = (float*)d_out;

    dim3 g1(HD / 128, (NB * LSEQ) / 128);   // (8, 256)
    xh_kernel<<<g1, 256>>>(x, emb, Wxh_w, Wxh_b, Whh_b, out);

    cudaFuncSetAttribute(rnn_persistent,
                         cudaFuncAttributeMaxDynamicSharedMemorySize,
                         RNN_SMEM_BYTES);
    rnn_persistent<<<NBLK, 256, RNN_SMEM_BYTES>>>(Whh_w, out);
}